// round 15
// baseline (speedup 1.0000x reference)
#include <cuda_runtime.h>
#include <cuda_fp16.h>
#include <cstdint>

// SpMM (COO, rows sorted): out[r,:] = sum_{e: rows[e]==r} vals[e] * embeds[cols[e],:]
// N=50000, E=800000, D=64, fp32 in/out. rows/cols int32.
//
// R15: spmm is now issue-bound (issue 50.8%, L2 24%, L1 34%). The per-edge
// instruction floor is dominated by 8 F2F + 8 FFMA per 4-edge warp-iter.
// Use Blackwell packed fma.rn.f32x2 (FFMA2, PTX-only) to halve the FFMA
// count; mov.b64 pairing is register-allocation-only (~0 SASS cost).
// Otherwise identical to R14 (half-warp/row, fp16 gather, fp32 accum).

#define D_FEAT    64
#define MAX_NODES 65537

__device__ int   g_row_ptr[MAX_NODES + 1];
__device__ uint2 g_emb[MAX_NODES * (D_FEAT / 4)];   // 2 half2 per uint2 = 4 feats

__global__ void prep(const int*   __restrict__ rows,
                     const float* __restrict__ embeds,
                     int n_edges, int n_nodes)
{
    const int tid    = blockIdx.x * blockDim.x + threadIdx.x;
    const int stride = gridDim.x * blockDim.x;

    // 1) row_ptr from sorted rows (boundary detection)
    for (int e = tid; e < n_edges; e += stride) {
        const int r    = rows[e];
        const int prev = (e == 0) ? -1 : rows[e - 1];
        for (int q = prev + 1; q <= r; q++) g_row_ptr[q] = e;     // N+1 total
        if (e == n_edges - 1)
            for (int q = r + 1; q <= n_nodes; q++) g_row_ptr[q] = n_edges;
    }

    // 2) embeds fp32 -> fp16 (4 floats -> 2 half2 -> 1 uint2)
    const int n_items = n_nodes * (D_FEAT / 4);
    const float4* __restrict__ emb4 = (const float4*)embeds;
    for (int i = tid; i < n_items; i += stride) {
        const float4 f = emb4[i];
        const __half2 h0 = __floats2half2_rn(f.x, f.y);
        const __half2 h1 = __floats2half2_rn(f.z, f.w);
        uint2 u;
        u.x = *reinterpret_cast<const unsigned int*>(&h0);
        u.y = *reinterpret_cast<const unsigned int*>(&h1);
        g_emb[i] = u;
    }
}

// acc(0,1) and acc(2,3) held as packed f32x2 pairs; 2x FFMA2 per edge-slice.
__device__ __forceinline__ void fma2x2(unsigned long long& a01,
                                       unsigned long long& a23,
                                       unsigned long long  vv, uint2 h)
{
    const __half2 h0 = *reinterpret_cast<const __half2*>(&h.x);
    const __half2 h1 = *reinterpret_cast<const __half2*>(&h.y);
    const float e0 = __low2float(h0), e1 = __high2float(h0);
    const float e2 = __low2float(h1), e3 = __high2float(h1);
    unsigned long long e01, e23;
    asm("mov.b64 %0, {%1, %2};" : "=l"(e01) : "f"(e0), "f"(e1));
    asm("mov.b64 %0, {%1, %2};" : "=l"(e23) : "f"(e2), "f"(e3));
    asm("fma.rn.f32x2 %0, %1, %2, %0;" : "+l"(a01) : "l"(e01), "l"(vv));
    asm("fma.rn.f32x2 %0, %1, %2, %0;" : "+l"(a23) : "l"(e23), "l"(vv));
}

__device__ __forceinline__ unsigned long long pack_vv(float v) {
    unsigned long long vv;
    asm("mov.b64 %0, {%1, %2};" : "=l"(vv) : "f"(v), "f"(v));
    return vv;
}

__global__ __launch_bounds__(256)
void spmm_csr(const int*   __restrict__ cols,
              const float* __restrict__ vals,
              float*       __restrict__ out,
              int n_nodes)
{
    const int warp = (blockIdx.x * blockDim.x + threadIdx.x) >> 5;
    const int lane = threadIdx.x & 31;

    const int half = lane >> 4;            // lanes 0-15: row 2w, 16-31: row 2w+1
    const int fl   = lane & 15;            // 4-feature slice (one uint2)

    const int row = 2 * warp + half;
    if (row >= n_nodes) return;

    const int start = g_row_ptr[row];
    const int end   = g_row_ptr[row + 1];

    unsigned long long a01 = 0ull, a23 = 0ull;   // packed f32x2 accumulators
    int e = start;

    // peel leading odd edge so pair metadata loads are 8B-aligned
    if (e < end && (e & 1)) {
        fma2x2(a01, a23, pack_vv(vals[e]), g_emb[cols[e] * (D_FEAT / 4) + fl]);
        e++;
    }

    // main pairwise loop (R9/R14-proven schedule): 2 independent 128B
    // gathers per iteration per half
    #pragma unroll 4
    for (; e + 1 < end; e += 2) {
        const int2   c2 = *(const int2*)  (cols + e);   // broadcast, L1-hit
        const float2 v2 = *(const float2*)(vals + e);
        const uint2  h0 = g_emb[c2.x * (D_FEAT / 4) + fl];
        const uint2  h1 = g_emb[c2.y * (D_FEAT / 4) + fl];
        fma2x2(a01, a23, pack_vv(v2.x), h0);
        fma2x2(a01, a23, pack_vv(v2.y), h1);
    }

    if (e < end)
        fma2x2(a01, a23, pack_vv(vals[e]), g_emb[cols[e] * (D_FEAT / 4) + fl]);

    // unpack accumulators and store: rows 2w,2w+1 adjacent -> 512B contiguous
    // warp store; covers every row (empty rows store zeros) -> no memset.
    float4 acc;
    asm("mov.b64 {%0, %1}, %2;" : "=f"(acc.x), "=f"(acc.y) : "l"(a01));
    asm("mov.b64 {%0, %1}, %2;" : "=f"(acc.z), "=f"(acc.w) : "l"(a23));
    ((float4*)out)[row * (D_FEAT / 4) + fl] = acc;
}

extern "C" void kernel_launch(void* const* d_in, const int* in_sizes, int n_in,
                              void* d_out, int out_size)
{
    const int*   rows   = (const int*)d_in[0];
    const int*   cols   = (const int*)d_in[1];
    const float* vals   = (const float*)d_in[2];
    const float* embeds = (const float*)d_in[3];
    float*       out    = (float*)d_out;

    const int n_edges = in_sizes[0];
    const int n_nodes = out_size / D_FEAT;

    prep<<<592, 256>>>(rows, embeds, n_edges, n_nodes);

    const int warps  = (n_nodes + 1) / 2;            // half-warp per row
    const int blocks = (warps * 32 + 255) / 256;
    spmm_csr<<<blocks, 256>>>(cols, vals, out, n_nodes);
}

// round 17
// speedup vs baseline: 1.3867x; 1.3867x over previous
#include <cuda_runtime.h>
#include <cuda_fp16.h>
#include <cstdint>

// SpMM (COO, rows sorted): out[r,:] = sum_{e: rows[e]==r} vals[e] * embeds[cols[e],:]
// N=50000, E=800000, D=64, fp32 in/out. rows/cols int32.
//
// R16: spmm is pipe-bound on F2F (half->float cvt, slow XU pipe): 4 F2F/edge
// ~= the whole 18.4us runtime at rt~8. Pre-combine edge PAIRS in fp16
// (hmul2 + hfma2 on the fast fma pipe), convert only the pair-sum:
// F2F per 2 edges drops 8 -> 4. fp32 accumulators; expected rel_err ~4-5e-4.
// Loop structure identical to R14 (the schedule ptxas handles best).

#define D_FEAT    64
#define MAX_NODES 65537

__device__ int   g_row_ptr[MAX_NODES + 1];
__device__ uint2 g_emb[MAX_NODES * (D_FEAT / 4)];   // 2 half2 per uint2 = 4 feats

__global__ void prep(const int*   __restrict__ rows,
                     const float* __restrict__ embeds,
                     int n_edges, int n_nodes)
{
    const int tid    = blockIdx.x * blockDim.x + threadIdx.x;
    const int stride = gridDim.x * blockDim.x;

    // 1) row_ptr from sorted rows (boundary detection)
    for (int e = tid; e < n_edges; e += stride) {
        const int r    = rows[e];
        const int prev = (e == 0) ? -1 : rows[e - 1];
        for (int q = prev + 1; q <= r; q++) g_row_ptr[q] = e;     // N+1 total
        if (e == n_edges - 1)
            for (int q = r + 1; q <= n_nodes; q++) g_row_ptr[q] = n_edges;
    }

    // 2) embeds fp32 -> fp16 (4 floats -> 2 half2 -> 1 uint2)
    const int n_items = n_nodes * (D_FEAT / 4);
    const float4* __restrict__ emb4 = (const float4*)embeds;
    for (int i = tid; i < n_items; i += stride) {
        const float4 f = emb4[i];
        const __half2 h0 = __floats2half2_rn(f.x, f.y);
        const __half2 h1 = __floats2half2_rn(f.z, f.w);
        uint2 u;
        u.x = *reinterpret_cast<const unsigned int*>(&h0);
        u.y = *reinterpret_cast<const unsigned int*>(&h1);
        g_emb[i] = u;
    }
}

// pair of edges: fp16 mul+fma on fma pipe, ONE convert of the pair-sum.
__device__ __forceinline__ void acc_pair(float4& acc, __half2 vv0, __half2 vv1,
                                         uint2 g0, uint2 g1)
{
    __half2 a = __hmul2(*reinterpret_cast<const __half2*>(&g0.x), vv0);
    __half2 b = __hmul2(*reinterpret_cast<const __half2*>(&g0.y), vv0);
    a = __hfma2(*reinterpret_cast<const __half2*>(&g1.x), vv1, a);
    b = __hfma2(*reinterpret_cast<const __half2*>(&g1.y), vv1, b);
    const float2 fa = __half22float2(a);
    const float2 fb = __half22float2(b);
    acc.x += fa.x; acc.y += fa.y;
    acc.z += fb.x; acc.w += fb.y;
}

// single edge (peel/tail)
__device__ __forceinline__ void acc_one(float4& acc, float v, uint2 g)
{
    const __half2 vv = __float2half2_rn(v);
    const __half2 a = __hmul2(*reinterpret_cast<const __half2*>(&g.x), vv);
    const __half2 b = __hmul2(*reinterpret_cast<const __half2*>(&g.y), vv);
    const float2 fa = __half22float2(a);
    const float2 fb = __half22float2(b);
    acc.x += fa.x; acc.y += fa.y;
    acc.z += fb.x; acc.w += fb.y;
}

__global__ __launch_bounds__(256)
void spmm_csr(const int*   __restrict__ cols,
              const float* __restrict__ vals,
              float*       __restrict__ out,
              int n_nodes)
{
    const int warp = (blockIdx.x * blockDim.x + threadIdx.x) >> 5;
    const int lane = threadIdx.x & 31;

    const int half = lane >> 4;            // lanes 0-15: row 2w, 16-31: row 2w+1
    const int fl   = lane & 15;            // 4-feature slice (one uint2)

    const int row = 2 * warp + half;
    if (row >= n_nodes) return;

    const int start = g_row_ptr[row];
    const int end   = g_row_ptr[row + 1];

    float4 acc = make_float4(0.f, 0.f, 0.f, 0.f);
    int e = start;

    // peel leading odd edge so pair metadata loads are 8B-aligned
    if (e < end && (e & 1)) {
        acc_one(acc, vals[e], g_emb[cols[e] * (D_FEAT / 4) + fl]);
        e++;
    }

    // main pairwise loop (R14-proven schedule): 2 independent 128B gathers
    // per iteration; fp16 pair-combine -> 4 F2F per 2 edges (was 8).
    #pragma unroll 4
    for (; e + 1 < end; e += 2) {
        const int2   c2 = *(const int2*)  (cols + e);   // broadcast, L1-hit
        const float2 v2 = *(const float2*)(vals + e);
        const uint2  h0 = g_emb[c2.x * (D_FEAT / 4) + fl];
        const uint2  h1 = g_emb[c2.y * (D_FEAT / 4) + fl];
        const __half2 hv = __floats2half2_rn(v2.x, v2.y);   // 1 pack
        acc_pair(acc, __low2half2(hv), __high2half2(hv), h0, h1);
    }

    if (e < end)
        acc_one(acc, vals[e], g_emb[cols[e] * (D_FEAT / 4) + fl]);

    // rows 2w,2w+1 adjacent -> 512B contiguous warp store; covers every row
    // (empty rows store zeros) -> no memset needed.
    ((float4*)out)[row * (D_FEAT / 4) + fl] = acc;
}

extern "C" void kernel_launch(void* const* d_in, const int* in_sizes, int n_in,
                              void* d_out, int out_size)
{
    const int*   rows   = (const int*)d_in[0];
    const int*   cols   = (const int*)d_in[1];
    const float* vals   = (const float*)d_in[2];
    const float* embeds = (const float*)d_in[3];
    float*       out    = (float*)d_out;

    const int n_edges = in_sizes[0];
    const int n_nodes = out_size / D_FEAT;

    prep<<<592, 256>>>(rows, embeds, n_edges, n_nodes);

    const int warps  = (n_nodes + 1) / 2;            // half-warp per row
    const int blocks = (warps * 32 + 255) / 256;
    spmm_csr<<<blocks, 256>>>(cols, vals, out, n_nodes);
}